// round 4
// baseline (speedup 1.0000x reference)
#include <cuda_runtime.h>

// ModelFilter: y = gain * clip(IIR2(FIR2(x)), -1, 1)
// Single fused chained-scan kernel (decoupled lookback over row tiles).
//   512 blocks x 256 threads; block = 32768-sample tile (8 blocks/row).
//   pass 1: per-thread zero-IC chunk states (CHUNK=128, step-2 companion form)
//   scan:   in-block Kogge-Stone over 256 chunk states
//   lookback: spin on predecessor block's inclusive row prefix (depth <= 7)
//   pass 2: true-IC replay (x re-read hits L2), clip*gain, streamed stores.

#define BATCH 64
#define TLEN  262144
#define CHUNK 128
#define CPB   256                      // chunks (=threads) per block
#define TILE  (CPB * CHUNK)            // 32768 samples per block
#define BPR   (TLEN / TILE)            // 8 blocks per row
#define NBLK  (BATCH * BPR)            // 512 blocks (one wave at 4/SM)
#define WIN   32
#define NW    (CHUNK / WIN)            // 4
#define PAD   (WIN + 1)                // 33

__device__ float2   g_pref[NBLK];      // published inclusive row prefixes
__device__ unsigned g_flag[NBLK];      // publish flags (re-zeroed per launch)
__device__ float4   g_P[9];            // A^(2^k), k=0..8, A = M^CHUNK

// ---------------------------------------------------------------------------
#define DSQR() { double t00 = m00*m00 + m01*m10, t01 = m00*m01 + m01*m11, \
                        t10 = m10*m00 + m11*m10, t11 = m10*m01 + m11*m11; \
                 m00 = t00; m01 = t01; m10 = t10; m11 = t11; }

__global__ void init_kernel(const float* __restrict__ ac)
{
    int t = threadIdx.x;
    if (t < NBLK) g_flag[t] = 0;
    if (t == 0) {
        double a0 = (double)ac[0];
        double a1 = (double)ac[1] / a0;
        double a2 = (double)ac[2] / a0;
        double m00 = -a1, m01 = -a2, m10 = 1.0, m11 = 0.0;
        #pragma unroll
        for (int i = 0; i < 7; i++) DSQR()               // A = M^128
        #pragma unroll
        for (int k = 0; k < 9; k++) {                    // A^(2^k), k=0..8
            g_P[k] = make_float4((float)m00, (float)m01, (float)m10, (float)m11);
            DSQR()
        }
    }
}

// ---------------------------------------------------------------------------
__global__ void __launch_bounds__(CPB, 4)
fused_kernel(const float* __restrict__ x, float* __restrict__ out,
             const float* __restrict__ ac, const float* __restrict__ bcf,
             const float* __restrict__ gain)
{
    __shared__ float  sx[CPB * PAD];     // 33.8 KB staging
    __shared__ float2 s[CPB];            // scan states
    __shared__ float4 sP[9];
    __shared__ float2 sE0;

    const int t   = threadIdx.x;
    const int row = blockIdx.x >> 3;     // BPR = 8
    const int rb  = blockIdx.x & (BPR - 1);
    const int slot = blockIdx.x;

    if (t < 9) sP[t] = g_P[t];

    const float a0 = __ldg(&ac[0]);
    const float a1 = __ldg(&ac[1]) / a0, a2 = __ldg(&ac[2]) / a0;
    const float b0 = __ldg(&bcf[0]) / a0, b1 = __ldg(&bcf[1]) / a0,
                b2 = __ldg(&bcf[2]) / a0;
    const float na1 = -a1, na2 = -a2;
    const float c00 = fmaf(a1, a1, -a2);     // a1^2 - a2
    const float c01 = a1 * a2;
    const float gn  = __ldg(&gain[0]);

    const float* xr  = x + (size_t)row * TLEN;
    const float4* xb4 = (const float4*)(xr + (size_t)rb * TILE);
    float4* ob4 = (float4*)(out + (size_t)row * TLEN + (size_t)rb * TILE);

    const int cir = rb * CPB + t;            // chunk index within row
    float xh1 = 0.0f, xh2 = 0.0f;            // true x history at chunk entry
    if (cir > 0) {
        int n0 = cir * CHUNK;
        xh1 = xr[n0 - 1];
        xh2 = xr[n0 - 2];
    }

    // ---------------- pass 1: zero-IC chunk end states ----------------
    float x1 = xh1, x2 = xh2;
    float y1 = 0.0f, y2 = 0.0f;

    for (int w = 0; w < NW; w++) {
        #pragma unroll
        for (int j = 0; j < 8; j++) {        // CPB*WIN/4 float4 total
            int idx = t + CPB * j;
            int c   = idx >> 3;              // WIN/4 = 8 float4 per chunk-win
            int off = idx & 7;
            float4 v = xb4[c * (CHUNK / 4) + w * (WIN / 4) + off];
            float* sp = &sx[c * PAD + off * 4];
            sp[0] = v.x; sp[1] = v.y; sp[2] = v.z; sp[3] = v.w;
        }
        __syncthreads();

        #pragma unroll
        for (int i = 0; i < WIN; i += 2) {
            float xn0 = sx[t * PAD + i];
            float xn1 = sx[t * PAD + i + 1];
            float f0 = fmaf(b2, x2, fmaf(b1, x1, b0 * xn0));
            float f1 = fmaf(b2, x1, fmaf(b1, xn0, b0 * xn1));
            float F1 = fmaf(na1, f0, f1);
            float t0 = fmaf(na2, y2, f0);
            float t1 = fmaf(c01, y2, F1);
            float yA = fmaf(na1, y1, t0);
            float yB = fmaf(c00, y1, t1);
            y2 = yA; y1 = yB;
            x2 = xn0; x1 = xn1;
        }
        __syncthreads();
    }

    // ---------------- in-block Kogge-Stone scan (256 states) ----------------
    float2 v = make_float2(y1, y2);
    s[t] = v;
    __syncthreads();

    #pragma unroll
    for (int k = 0; k < 8; k++) {
        const int o = 1 << k;
        float4 P = sP[k];
        float2 u = (t >= o) ? s[t - o] : make_float2(0.0f, 0.0f);
        __syncthreads();
        if (t >= o) {
            v.x = fmaf(P.x, u.x, fmaf(P.y, u.y, v.x));
            v.y = fmaf(P.z, u.x, fmaf(P.w, u.y, v.y));
        }
        s[t] = v;
        __syncthreads();
    }

    // ---------------- lookback + publish ----------------
    if (t == 0) {
        float2 E0 = make_float2(0.0f, 0.0f);
        if (rb > 0) {
            volatile unsigned* fl = &g_flag[slot - 1];
            while (*fl == 0u) __nanosleep(64);
            __threadfence();
            volatile float* pp = (volatile float*)&g_pref[slot - 1];
            E0.x = pp[0];
            E0.y = pp[1];
        }
        // inclusive prefix of this block = A^256 * E0 + local aggregate
        float2 agg = s[CPB - 1];
        float4 A256 = sP[8];
        float2 inc;
        inc.x = fmaf(A256.x, E0.x, fmaf(A256.y, E0.y, agg.x));
        inc.y = fmaf(A256.z, E0.x, fmaf(A256.w, E0.y, agg.y));
        g_pref[slot] = inc;
        __threadfence();
        g_flag[slot] = 1u;
        sE0 = E0;
    }
    __syncthreads();

    // true init of chunk t: A^t * E0 + s[t-1]
    float2 E0 = sE0;
    float2 w2 = E0;
    #pragma unroll
    for (int k = 0; k < 8; k++) {
        if ((t >> k) & 1) {
            float4 P = sP[k];
            float2 nw;
            nw.x = fmaf(P.x, w2.x, P.y * w2.y);
            nw.y = fmaf(P.z, w2.x, P.w * w2.y);
            w2 = nw;
        }
    }
    float2 se = (t == 0) ? make_float2(0.0f, 0.0f) : s[t - 1];
    y1 = w2.x + se.x;
    y2 = w2.y + se.y;

    // ---------------- pass 2: true-IC replay, clip*gain, store ----------------
    x1 = xh1; x2 = xh2;
    __syncthreads();     // protect s[] reads above before sx reuse below

    for (int w = 0; w < NW; w++) {
        #pragma unroll
        for (int j = 0; j < 8; j++) {
            int idx = t + CPB * j;
            int c   = idx >> 3;
            int off = idx & 7;
            float4 vv = __ldg(&xb4[c * (CHUNK / 4) + w * (WIN / 4) + off]);
            float* sp = &sx[c * PAD + off * 4];
            sp[0] = vv.x; sp[1] = vv.y; sp[2] = vv.z; sp[3] = vv.w;
        }
        __syncthreads();

        #pragma unroll
        for (int i = 0; i < WIN; i += 2) {
            float xn0 = sx[t * PAD + i];
            float xn1 = sx[t * PAD + i + 1];
            float f0 = fmaf(b2, x2, fmaf(b1, x1, b0 * xn0));
            float f1 = fmaf(b2, x1, fmaf(b1, xn0, b0 * xn1));
            float F1 = fmaf(na1, f0, f1);
            float t0 = fmaf(na2, y2, f0);
            float t1 = fmaf(c01, y2, F1);
            float yA = fmaf(na1, y1, t0);
            float yB = fmaf(c00, y1, t1);
            y2 = yA; y1 = yB;
            x2 = xn0; x1 = xn1;
            sx[t * PAD + i]     = fminf(fmaxf(yA, -1.0f), 1.0f) * gn;
            sx[t * PAD + i + 1] = fminf(fmaxf(yB, -1.0f), 1.0f) * gn;
        }
        __syncthreads();

        #pragma unroll
        for (int j = 0; j < 8; j++) {
            int idx = t + CPB * j;
            int c   = idx >> 3;
            int off = idx & 7;
            const float* sp = &sx[c * PAD + off * 4];
            float4 vv;
            vv.x = sp[0]; vv.y = sp[1]; vv.z = sp[2]; vv.w = sp[3];
            __stcs(&ob4[c * (CHUNK / 4) + w * (WIN / 4) + off], vv);
        }
        __syncthreads();
    }
}

// ---------------------------------------------------------------------------
extern "C" void kernel_launch(void* const* d_in, const int* in_sizes, int n_in,
                              void* d_out, int out_size)
{
    const float* x    = (const float*)d_in[0];
    const float* a    = (const float*)d_in[1];
    const float* b    = (const float*)d_in[2];
    const float* gain = (const float*)d_in[3];
    float* out = (float*)d_out;

    init_kernel<<<1, NBLK>>>(a);
    fused_kernel<<<NBLK, CPB>>>(x, out, a, b, gain);
}